// round 11
// baseline (speedup 1.0000x reference)
#include <cuda_runtime.h>
#include <cuda_bf16.h>
#include <cstdint>

// Problem constants (from reference)
#define H_IMG 240
#define W_IMG 135
#define NPIX  (H_IMG * W_IMG)   // 32400
#define NV    600
#define NF    1000
#define SIGMA_F 1e-4f
#define BLUR_F  9.210240366975850e-4f   // log(1/1e-4 - 1) * 1e-4
#define MARGIN_F 0.032f                 // > sqrt(BLUR_F) = 0.030348
#define F_LEN_F 1000.0f
#define C_PP_F  512.0f
#define CAM_F   1024.0f

// Conservative near-band threshold on NORMALIZED line distance:
// sqrt(BLUR) = 0.0303484; margin >> fp32 abs error of the L ffma chain.
#define SQRT_BLUR_SAFE 0.0306f
// SAT cull margin: sqrt(BLUR) + fp slack (cull only when provably unaffected)
#define SAT_MARGIN 0.032f

#define TILE_W 16
#define TILE_H 16
#define TILES_X 9     // ceil(135/16)
#define TILES_Y 15    // 240/16
#define NTILES  (TILES_X * TILES_Y)   // 135
#define NGROUP  8                      // 135*8 = 1080 CTAs -> single wave @ 8 CTA/SM
#define FACES_PER_G (NF / NGROUP)      // 125
#define TPB 256

// Once acc <= DONE_THRESH for all lanes, every remaining face term is <= 0,
// so the full-group partial is <= DONE_THRESH, hence total <= DONE_THRESH and
// alpha == 1.0f bit-exactly — same as the reference.
#define DONE_THRESH (-100.0f)
#define SENTINEL    (-1e30f)

// Cross-CTA communication (device globals; zero-init at load, reset by kernel)
__device__ float g_acc[NTILES * NGROUP * TPB];  // per (tile, group, thread) partial
__device__ float g_tilepart[NTILES];            // per-tile |diff| sums
__device__ int   g_tile_ticket[NTILES];
__device__ int   g_global_ticket;

// grid: (TILES_X, TILES_Y, NGROUP), block: (16,16)
__global__ void __launch_bounds__(TPB, 8)
fused_sil_kernel(const float* __restrict__ verts,
                 const float* __restrict__ gt,
                 const int*   __restrict__ faces,
                 float* __restrict__ out) {
    // fast-path data, 3 float4/face: (nkx, nky, ck, inv_k) per edge k
    //   L_k = nkx*px + nky*py + ck  (normalized line distance, sign = cross sign)
    // slow-path data, 3 float4/face: (akx, aky, ab_kx, ab_ky) per edge k
    __shared__ float4 s_fast[FACES_PER_G * 3];
    __shared__ float4 s_slow[FACES_PER_G * 3];
    __shared__ float  s_red[TPB];
    __shared__ int    s_wcnt[8];
    __shared__ int    s_n;
    __shared__ int    s_flag;

    int tid  = threadIdx.y * 16 + threadIdx.x;
    int wid  = tid >> 5;
    int lane = tid & 31;

    int gx   = blockIdx.x * TILE_W;
    int gy   = blockIdx.y * TILE_H;
    int grp  = blockIdx.z;
    int tile = blockIdx.y * TILES_X + blockIdx.x;

    // tile pixel-center bounds and center
    float tx0 = (float)gx + 0.5f;
    float tx1 = (float)gx + (float)(TILE_W - 1) + 0.5f;
    float ty0 = (float)gy + 0.5f;
    float ty1 = (float)gy + (float)(TILE_H - 1) + 0.5f;
    float cxc = 0.5f * (tx0 + tx1);   // gx + 8.0
    float cyc = 0.5f * (ty0 + ty1);
    const float HW = 0.5f * (float)(TILE_W - 1);   // 7.5 (pixel-center half-extent)
    const float HH = 0.5f * (float)(TILE_H - 1);   // 7.5

    // ---- per-CTA face precompute (registers) + cull (bbox AND edge-SAT) ----
    bool pass = false;
    float4 eF0, eF1, eF2, eS0, eS1, eS2;
    if (tid < FACES_PER_G) {
        int f = grp * FACES_PER_G + tid;
        float pxv[3], pyv[3];
        float tz = 0.0f;
#pragma unroll
        for (int k = 0; k < 3; k++) {
            int vi = faces[f * 3 + k];
            float x = verts[vi * 3 + 0];
            float y = verts[vi * 3 + 1];
            float z = verts[vi * 3 + 2];
            float vx = -x, vy = -y, vz = z;      // R = diag(-1,-1,1)
            tz += vz;
            float zc = fmaxf(vz, 1e-6f);
            pxv[k] = (F_LEN_F * vx / zc + C_PP_F) / CAM_F * (float)W_IMG;
            pyv[k] = (F_LEN_F * vy / zc + C_PP_F) / CAM_F * (float)H_IMG;
        }
        tz *= (1.0f / 3.0f);

        // winding sign: sign of cross(e0, e1) (= 2*signed area)
        float e0x = pxv[1] - pxv[0], e0y = pyv[1] - pyv[0];
        float e1x = pxv[2] - pxv[1], e1y = pyv[2] - pyv[1];
        float area2 = e0x * e1y - e0y * e1x;
        float s = (area2 >= 0.0f) ? 1.0f : -1.0f;

        float4 fast[3], slow[3];
        bool sat = true;
#pragma unroll
        for (int k = 0; k < 3; k++) {
            int k2 = (k + 1) % 3;
            float ax = pxv[k],  ay = pyv[k];
            float abx = pxv[k2] - ax, aby = pyv[k2] - ay;
            float dd  = abx * abx + aby * aby + 1e-12f;
            float inv = 1.0f / dd;
            float rlen = rsqrtf(dd);
            float nx = -aby * rlen;
            float ny =  abx * rlen;
            float c  = -(nx * ax + ny * ay);
            fast[k] = make_float4(nx, ny, c, inv);
            slow[k] = make_float4(ax, ay, abx, aby);

            // SAT on edge k: any affected pixel p has s*L_k(p) >= -sqrt(BLUR)
            // (inside => s*L_k >= 0; near => Lipschitz gives >= -0.0304).
            // If the tile's MAX of s*L_k is below -SAT_MARGIN, no pixel of
            // this tile can be affected by this face. Degenerate edges give
            // n=(0,0), L=0 -> never cull (conservative).
            float Lc = fmaf(nx, cxc, fmaf(ny, cyc, c));
            float maxL = s * Lc + (fabsf(nx) + fabsf(ny)) * HW;  // HW==HH
            sat = sat && (maxL >= -SAT_MARGIN);
        }
        eF0 = fast[0]; eF1 = fast[1]; eF2 = fast[2];
        eS0 = slow[0]; eS1 = slow[1]; eS2 = slow[2];

        if (tz > 1e-6f) {
            float xmn = fminf(pxv[0], fminf(pxv[1], pxv[2])) - MARGIN_F;
            float xmx = fmaxf(pxv[0], fmaxf(pxv[1], pxv[2])) + MARGIN_F;
            float ymn = fminf(pyv[0], fminf(pyv[1], pyv[2])) - MARGIN_F;
            float ymx = fmaxf(pyv[0], fmaxf(pyv[1], pyv[2])) + MARGIN_F;
            pass = (xmn <= tx1) && (xmx >= tx0) && (ymn <= ty1) && (ymx >= ty0)
                   && sat;
        }
    }

    // ---- deterministic ordered compaction of face DATA into smem ----
    unsigned mask = __ballot_sync(0xffffffffu, pass);
    if (lane == 0) s_wcnt[wid] = __popc(mask);
    __syncthreads();
    int woff = 0;
#pragma unroll
    for (int w = 0; w < 8; w++)
        if (w < wid) woff += s_wcnt[w];
    if (pass) {
        int pos = woff + __popc(mask & ((1u << lane) - 1u));
        s_fast[pos * 3 + 0] = eF0;
        s_fast[pos * 3 + 1] = eF1;
        s_fast[pos * 3 + 2] = eF2;
        s_slow[pos * 3 + 0] = eS0;
        s_slow[pos * 3 + 1] = eS1;
        s_slow[pos * 3 + 2] = eS2;
    }
    if (tid == 0) {
        int tot = 0;
#pragma unroll
        for (int w = 0; w < 8; w++) tot += s_wcnt[w];
        s_n = tot;
    }
    __syncthreads();
    int nf = s_n;

    // ---- per-pixel loop over compacted faces (broadcast LDS) ----
    int xi = gx + threadIdx.x;
    int yi = gy + threadIdx.y;
    float px = (float)xi + 0.5f;
    float py = (float)yi + 0.5f;

    float acc = 0.0f;
    for (int i = 0; i < nf; i++) {
        float4 f0 = s_fast[i * 3 + 0];
        float4 f1 = s_fast[i * 3 + 1];
        float4 f2 = s_fast[i * 3 + 2];

        // normalized signed line distances (sign == cross sign)
        float L0 = fmaf(f0.x, px, fmaf(f0.y, py, f0.z));
        float L1 = fmaf(f1.x, px, fmaf(f1.y, py, f1.z));
        float L2 = fmaf(f2.x, px, fmaf(f2.y, py, f2.z));

        float Lmn = fminf(L0, fminf(L1, L2));
        float Lmx = fmaxf(L0, fmaxf(L1, L2));
        bool inside = (Lmn >= 0.0f) || (Lmx <= 0.0f);

        // conservative near test: min line distance <= safe threshold.
        // seg-dist >= line-dist per edge, so min|L| > thr  =>  d2min > BLUR.
        float amn = fminf(fabsf(L0), fminf(fabsf(L1), fabsf(L2)));

        if (inside || (amn <= SQRT_BLUR_SAFE)) {
            // exact segment-distance path (R4 math, inv packed in f_k.w)
            float4 s0 = s_slow[i * 3 + 0];
            float4 s1 = s_slow[i * 3 + 1];
            float4 s2 = s_slow[i * 3 + 2];

            float ap0x = px - s0.x, ap0y = py - s0.y;
            float t0 = fminf(fmaxf((ap0x * s0.z + ap0y * s0.w) * f0.w, 0.0f), 1.0f);
            float q0x = ap0x - t0 * s0.z, q0y = ap0y - t0 * s0.w;
            float d0 = q0x * q0x + q0y * q0y;

            float ap1x = px - s1.x, ap1y = py - s1.y;
            float t1 = fminf(fmaxf((ap1x * s1.z + ap1y * s1.w) * f1.w, 0.0f), 1.0f);
            float q1x = ap1x - t1 * s1.z, q1y = ap1y - t1 * s1.w;
            float d1 = q1x * q1x + q1y * q1y;

            float ap2x = px - s2.x, ap2y = py - s2.y;
            float t2 = fminf(fmaxf((ap2x * s2.z + ap2y * s2.w) * f2.w, 0.0f), 1.0f);
            float q2x = ap2x - t2 * s2.z, q2y = ap2y - t2 * s2.w;
            float d2 = q2x * q2x + q2y * q2y;

            float d2min = fminf(d0, fminf(d1, d2));

            if (inside || (d2min <= BLUR_F)) {
                float xarg = (inside ? d2min : -d2min) * (1.0f / SIGMA_F);
                acc -= log1pf(__expf(xarg));   // -softplus, exact R4/R7 form
            }
        }

        // Warp early exit (output-invisible, see R7): publish uniform sentinel.
        if (__ballot_sync(0xffffffffu, acc > DONE_THRESH) == 0u) {
            acc = SENTINEL;
            break;
        }
    }

    // publish this group's partial (release: store -> fence -> ticket RMW)
    __stcg(&g_acc[(tile * NGROUP + grp) * TPB + tid], acc);
    __threadfence();

    // ---- per-tile ticket: last group CTA combines this tile ----
    if (tid == 0) {
        int old = atomicAdd(&g_tile_ticket[tile], 1);
        s_flag = (old == NGROUP - 1) ? 1 : 0;
        __threadfence();   // ACQUIRE side: pairs with writers' release fences
    }
    __syncthreads();
    if (s_flag == 0) return;

    // combine groups for this tile — FIXED order (deterministic)
    float total = 0.0f;
#pragma unroll
    for (int g = 0; g < NGROUP; g++)
        total += __ldcg(&g_acc[(tile * NGROUP + g) * TPB + tid]);
    float alpha = (total < -87.0f) ? 1.0f : (1.0f - __expf(total));

    float diff = 0.0f;
    if (xi < W_IMG) {   // yi always < H_IMG (240 = 15*16)
        int pix = yi * W_IMG + xi;
        out[1 + pix] = alpha;
        diff = fabsf(alpha - gt[pix]);
    }

    // block-reduce |diff|
    s_red[tid] = diff;
    __syncthreads();
#pragma unroll
    for (int off = 128; off > 0; off >>= 1) {
        if (tid < off) s_red[tid] += s_red[tid + off];
        __syncthreads();
    }
    if (tid == 0) {
        __stcg(&g_tilepart[tile], s_red[0]);
        __threadfence();   // release for g_tilepart
        int t = atomicAdd(&g_global_ticket, 1);
        s_flag = (t == NTILES - 1) ? 2 : 0;
        __threadfence();   // ACQUIRE side for the final-stage loads
    }
    __syncthreads();
    if (s_flag != 2) return;

    // ---- final: last tile sums 135 tile partials (fixed order) + resets ----
    float v = (tid < NTILES) ? __ldcg(&g_tilepart[tid]) : 0.0f;
    s_red[tid] = v;
    __syncthreads();
#pragma unroll
    for (int off = 128; off > 0; off >>= 1) {
        if (tid < off) s_red[tid] += s_red[tid + off];
        __syncthreads();
    }
    if (tid == 0) out[0] = s_red[0] * (1.0f / (float)NPIX);

    // reset tickets for next graph replay
    if (tid < NTILES) g_tile_ticket[tid] = 0;
    if (tid == 0) g_global_ticket = 0;
}

extern "C" void kernel_launch(void* const* d_in, const int* in_sizes, int n_in,
                              void* d_out, int out_size) {
    const float* verts = (const float*)d_in[0];
    const float* gt    = (const float*)d_in[1];
    const int*   faces = (const int*)d_in[2];
    float* out = (float*)d_out;

    dim3 grid(TILES_X, TILES_Y, NGROUP);
    dim3 block(16, 16);
    fused_sil_kernel<<<grid, block>>>(verts, gt, faces, out);
}